// round 16
// baseline (speedup 1.0000x reference)
#include <cuda_runtime.h>
#include <math.h>

#define HH 1024
#define WW 1024
#define NPIX (HH * WW)
#define N_ITERS 100

#define NBLK 888            // 148 SMs x 6 blocks — co-resident by construction
#define NTHR 256
#define NTILES 4096         // 32x128 grid of 32x8 tiles
#define MAX_TPB 5           // ceil(4096/888)

// ---------------- device scratch ----------------
__device__ float  g_Y[NPIX];
__device__ float2 g_x0[NPIX];       // ping
__device__ float2 g_x1[NPIX];       // pong
__device__ unsigned int g_count;            // monotonic barrier tickets
__device__ volatile unsigned int g_phase;   // monotonic barrier generation

__device__ __forceinline__ float luma(float r, float g, float b) {
    return (0.3f * r + 0.59f * g + 0.11f * b) * (1.0f / 255.0f);
}

__device__ __forceinline__ void unpack_w(uint4 q, float* w, float& c) {
    const float S = 1.0f / 65535.0f;
    w[0] = (float)(q.x & 0xFFFFu) * S;  w[1] = (float)(q.x >> 16) * S;
    w[2] = (float)(q.y & 0xFFFFu) * S;  w[3] = (float)(q.y >> 16) * S;
    w[4] = (float)(q.z & 0xFFFFu) * S;  w[5] = (float)(q.z >> 16) * S;
    w[6] = (float)(q.w & 0xFFFFu) * S;  w[7] = (float)(q.w >> 16) * S;
    c = ((q.x | q.y | q.z | q.w) == 0u) ? 1.0f : 0.0f;
}

// replay-safe grid barrier: monotonic group tickets, one fence per block side.
// Pre-arrive __threadfence = release (cumulative over block via __syncthreads)
// Post-wait  __threadfence = acquire + CCTL.IVALL (fresh L1 for next iter)
__device__ __forceinline__ void grid_barrier(int tid) {
    __syncthreads();
    if (tid == 0) {
        __threadfence();
        unsigned int a = atomicAdd(&g_count, 1u);
        unsigned int group = a / (unsigned int)NBLK;
        if ((a + 1u) % (unsigned int)NBLK == 0u) {
            g_phase = group + 1u;                    // single writer per value
        } else {
            while (g_phase < group + 1u) { __nanosleep(64); }
        }
        __threadfence();
    }
    __syncthreads();
}

// R12-identical stencil body, weights from smem
__device__ __forceinline__ float2 stencil_px(const float2* __restrict__ xin,
                                             int i, int j, uint4 q) {
    int im = (i > 0)      ? i - 1 : 0;
    int ip = (i < HH - 1) ? i + 1 : HH - 1;
    int jm = (j > 0)      ? j - 1 : 0;
    int jp = (j < WW - 1) ? j + 1 : WW - 1;

    const float2* rm = xin + im * WW;
    const float2* r0 = xin + i  * WW;
    const float2* rp = xin + ip * WW;

    float w[8], c;
    unpack_w(q, w, c);

    float2 ctr = r0[j];
    float ax = c * ctr.x, ay = c * ctr.y;
    float2 t;
    t = rm[jm]; ax = fmaf(w[0], t.x, ax); ay = fmaf(w[0], t.y, ay);
    t = rm[j ]; ax = fmaf(w[1], t.x, ax); ay = fmaf(w[1], t.y, ay);
    t = rm[jp]; ax = fmaf(w[2], t.x, ax); ay = fmaf(w[2], t.y, ay);
    t = r0[jm]; ax = fmaf(w[3], t.x, ax); ay = fmaf(w[3], t.y, ay);
    t = r0[jp]; ax = fmaf(w[4], t.x, ax); ay = fmaf(w[4], t.y, ay);
    t = rp[jm]; ax = fmaf(w[5], t.x, ax); ay = fmaf(w[5], t.y, ay);
    t = rp[j ]; ax = fmaf(w[6], t.x, ax); ay = fmaf(w[6], t.y, ay);
    t = rp[jp]; ax = fmaf(w[7], t.x, ax); ay = fmaf(w[7], t.y, ay);
    return make_float2(ax, ay);
}

// ---------------- the whole pipeline in one persistent kernel ----------------
__global__ void __launch_bounds__(NTHR, 6)
persist_kernel(const float* __restrict__ gray,
               const float* __restrict__ app,
               float* __restrict__ out) {
    __shared__ uint4 s_wq[MAX_TPB * NTHR];   // 20 KB: own-pixel weights per tile

    int tid = threadIdx.x;
    int b   = blockIdx.x;
    int tx  = tid & 31, ty = tid >> 5;

    // ---------- prep phase: weights (to smem), Y, x0 for own tiles ----------
    #pragma unroll 1
    for (int k = 0; k < MAX_TPB; k++) {
        int t = b + k * NBLK;
        if (t >= NTILES) break;
        int i = (t >> 5) * 8 + ty;           // tile row group
        int j = (t & 31) * 32 + tx;          // tile col group
        int pix = i * WW + j;

        float g0 = gray[3*pix+0], g1 = gray[3*pix+1], g2 = gray[3*pix+2];
        float a0 = app [3*pix+0], a1 = app [3*pix+1], a2 = app [3*pix+2];

        const float inv255 = 1.0f / 255.0f;
        float diff = (fabsf(g0-a0) + fabsf(g1-a1) + fabsf(g2-a2)) * inv255;
        bool colored = diff > 0.01f;

        float Y = luma(g0, g1, g2);
        float ya = luma(a0, a1, a2);
        float r  = a0 * inv255;
        float bl = a2 * inv255;
        float I = 0.74f*(r - ya) - 0.27f*(bl - ya);
        float Q = 0.48f*(r - ya) + 0.41f*(bl - ya);

        g_Y[pix]  = Y;
        g_x0[pix] = colored ? make_float2(I, Q) : make_float2(0.0f, 0.0f);

        const int di[8] = {-1,-1,-1, 0, 0, 1, 1, 1};
        const int dj[8] = {-1, 0, 1,-1, 1,-1, 0, 1};
        float nbr[8], valid[8];
        #pragma unroll
        for (int m = 0; m < 8; m++) {
            int ii = i + di[m], jj = j + dj[m];
            bool in = (ii >= 0) & (ii < HH) & (jj >= 0) & (jj < WW);
            valid[m] = in ? 1.0f : 0.0f;
            if (in) {
                int np = (ii * WW + jj) * 3;
                nbr[m] = luma(gray[np], gray[np+1], gray[np+2]);
            } else nbr[m] = 0.0f;
        }

        float count = 1.0f, s = Y;
        #pragma unroll
        for (int m = 0; m < 8; m++) { count += valid[m]; s += nbr[m] * valid[m]; }
        float mean = s / count;

        float var = (Y - mean) * (Y - mean);
        #pragma unroll
        for (int m = 0; m < 8; m++) {
            float d = nbr[m] - mean;
            var += d * d * valid[m];
        }
        var /= count;
        float vs = fmaxf(0.6f * var, 2e-6f);
        float inv_vs = 1.0f / vs;

        float w[8], wsum = 0.0f;
        #pragma unroll
        for (int m = 0; m < 8; m++) {
            float d = nbr[m] - Y;
            w[m] = expf(-d * d * inv_vs) * valid[m];
            wsum += w[m];
        }
        float scale = (colored ? 0.0f : 1.0f) / wsum * 65535.0f;

        unsigned int u[8];
        #pragma unroll
        for (int m = 0; m < 8; m++) u[m] = (unsigned int)rintf(w[m] * scale);

        uint4 q;
        q.x = u[0] | (u[1] << 16);
        q.y = u[2] | (u[3] << 16);
        q.z = u[4] | (u[5] << 16);
        q.w = u[6] | (u[7] << 16);
        s_wq[k * NTHR + tid] = q;
    }

    grid_barrier(tid);   // all x0 visible everywhere

    // ---------- 100 iterations ----------
    #pragma unroll 1
    for (int it = 0; it < N_ITERS; it++) {
        const float2* __restrict__ xin  = (it & 1) ? g_x1 : g_x0;
        float2*       __restrict__ xout = (it & 1) ? g_x0 : g_x1;
        bool last = (it == N_ITERS - 1);

        #pragma unroll 1
        for (int k = 0; k < MAX_TPB; k++) {
            int t = b + k * NBLK;
            if (t >= NTILES) break;
            int i = (t >> 5) * 8 + ty;
            int j = (t & 31) * 32 + tx;
            int pix = i * WW + j;

            float2 v = stencil_px(xin, i, j, s_wq[k * NTHR + tid]);

            if (!last) {
                xout[pix] = v;
            } else {
                // final: YIQ -> RGB straight from registers
                float y = g_Y[pix];
                float I = v.x, Q = v.y;
                float r  = y + 0.9468822170900693f  * I + 0.6235565819861433f * Q;
                float g  = y - 0.27478764629897834f * I - 0.6356910791873801f * Q;
                float bb = y - 1.1085450346420322f  * I + 1.7090069284064666f * Q;
                int o = 3 * pix;
                out[o+0] = fminf(fmaxf(r,  0.0f), 1.0f) * 255.0f;
                out[o+1] = fminf(fmaxf(g,  0.0f), 1.0f) * 255.0f;
                out[o+2] = fminf(fmaxf(bb, 0.0f), 1.0f) * 255.0f;
            }
        }

        if (!last) grid_barrier(tid);   // no barrier after the final write-out
    }
}

extern "C" void kernel_launch(void* const* d_in, const int* in_sizes, int n_in,
                              void* d_out, int out_size) {
    const float* gray = (const float*)d_in[0];
    const float* app  = (const float*)d_in[1];
    float* out = (float*)d_out;

    persist_kernel<<<NBLK, NTHR>>>(gray, app, out);
}

// round 17
// speedup vs baseline: 1.5144x; 1.5144x over previous
#include <cuda_runtime.h>
#include <math.h>

#define HH 1024
#define WW 1024
#define NPIX (HH * WW)
#define N_ITERS 100

// ---------------- device scratch (statically allocated, ~36 MB) ----------------
__device__ uint4  g_wq[NPIX];       // 8x unorm16 weights per pixel (16B)
__device__ float  g_Y[NPIX];        // luminance plane
__device__ float2 g_x0[NPIX];       // ping
__device__ float2 g_x1[NPIX];       // pong

__device__ __forceinline__ float luma(float r, float g, float b) {
    return (0.3f * r + 0.59f * g + 0.11f * b) * (1.0f / 255.0f);
}

// ---------------- prep: setup + weights fused (one pass) ----------------
// Seeds BOTH x buffers with b so colored pixels (all-zero weights) never need
// to be computed or stored again.
__global__ void prep_kernel(const float* __restrict__ gray,
                            const float* __restrict__ app) {
    int pix = blockIdx.x * blockDim.x + threadIdx.x;
    if (pix >= NPIX) return;
    int i = pix / WW, j = pix % WW;

    float g0 = gray[3*pix+0], g1 = gray[3*pix+1], g2 = gray[3*pix+2];
    float a0 = app [3*pix+0], a1 = app [3*pix+1], a2 = app [3*pix+2];

    const float inv255 = 1.0f / 255.0f;
    float diff = (fabsf(g0-a0) + fabsf(g1-a1) + fabsf(g2-a2)) * inv255;
    bool colored = diff > 0.01f;

    float Y = luma(g0, g1, g2);

    float ya = luma(a0, a1, a2);
    float r  = a0 * inv255;
    float bl = a2 * inv255;
    float I = 0.74f*(r - ya) - 0.27f*(bl - ya);
    float Q = 0.48f*(r - ya) + 0.41f*(bl - ya);

    float2 b = colored ? make_float2(I, Q) : make_float2(0.0f, 0.0f);
    g_Y[pix]  = Y;
    g_x0[pix] = b;
    g_x1[pix] = b;      // colored slots must be valid in BOTH buffers forever

    const int di[8] = {-1,-1,-1, 0, 0, 1, 1, 1};
    const int dj[8] = {-1, 0, 1,-1, 1,-1, 0, 1};

    float nbr[8], valid[8];
    #pragma unroll
    for (int k = 0; k < 8; k++) {
        int ii = i + di[k], jj = j + dj[k];
        bool in = (ii >= 0) & (ii < HH) & (jj >= 0) & (jj < WW);
        valid[k] = in ? 1.0f : 0.0f;
        if (in) {
            int np = (ii * WW + jj) * 3;
            nbr[k] = luma(gray[np], gray[np+1], gray[np+2]);
        } else {
            nbr[k] = 0.0f;
        }
    }

    float count = 1.0f, s = Y;
    #pragma unroll
    for (int k = 0; k < 8; k++) { count += valid[k]; s += nbr[k] * valid[k]; }
    float mean = s / count;

    float var = (Y - mean) * (Y - mean);
    #pragma unroll
    for (int k = 0; k < 8; k++) {
        float d = nbr[k] - mean;
        var += d * d * valid[k];
    }
    var /= count;
    float vs = fmaxf(0.6f * var, 2e-6f);
    float inv_vs = 1.0f / vs;

    float w[8], wsum = 0.0f;
    #pragma unroll
    for (int k = 0; k < 8; k++) {
        float d = nbr[k] - Y;
        w[k] = expf(-d * d * inv_vs) * valid[k];
        wsum += w[k];
    }
    // colored pixels: all weights 0 (the all-zero pattern encodes "colored")
    float scale = (colored ? 0.0f : 1.0f) / wsum * 65535.0f;

    unsigned int u[8];
    #pragma unroll
    for (int k = 0; k < 8; k++) u[k] = (unsigned int)rintf(w[k] * scale);

    uint4 q;
    q.x = u[0] | (u[1] << 16);
    q.y = u[2] | (u[3] << 16);
    q.z = u[4] | (u[5] << 16);
    q.w = u[6] | (u[7] << 16);
    g_wq[pix] = q;
}

__device__ __forceinline__ void unpack_w8(uint4 q, float* w) {
    const float S = 1.0f / 65535.0f;
    w[0] = (float)(q.x & 0xFFFFu) * S;  w[1] = (float)(q.x >> 16) * S;
    w[2] = (float)(q.y & 0xFFFFu) * S;  w[3] = (float)(q.y >> 16) * S;
    w[4] = (float)(q.z & 0xFFFFu) * S;  w[5] = (float)(q.z >> 16) * S;
    w[6] = (float)(q.w & 0xFFFFu) * S;  w[7] = (float)(q.w >> 16) * S;
}

// 8-tap sum (no center tap — center contribution is exactly 0 for every pixel
// this result is stored for; colored pixels are never stored)
__device__ __forceinline__ float2 taps8(const float2* __restrict__ xin,
                                        int i, int j, const float* w) {
    int im = (i > 0)      ? i - 1 : 0;
    int ip = (i < HH - 1) ? i + 1 : HH - 1;
    int jm = (j > 0)      ? j - 1 : 0;
    int jp = (j < WW - 1) ? j + 1 : WW - 1;

    const float2* rm = xin + im * WW;
    const float2* r0 = xin + i  * WW;
    const float2* rp = xin + ip * WW;

    float ax = 0.0f, ay = 0.0f;
    float2 t;
    t = rm[jm]; ax = fmaf(w[0], t.x, ax); ay = fmaf(w[0], t.y, ay);
    t = rm[j ]; ax = fmaf(w[1], t.x, ax); ay = fmaf(w[1], t.y, ay);
    t = rm[jp]; ax = fmaf(w[2], t.x, ax); ay = fmaf(w[2], t.y, ay);
    t = r0[jm]; ax = fmaf(w[3], t.x, ax); ay = fmaf(w[3], t.y, ay);
    t = r0[jp]; ax = fmaf(w[4], t.x, ax); ay = fmaf(w[4], t.y, ay);
    t = rp[jm]; ax = fmaf(w[5], t.x, ax); ay = fmaf(w[5], t.y, ay);
    t = rp[j ]; ax = fmaf(w[6], t.x, ax); ay = fmaf(w[6], t.y, ay);
    t = rp[jp]; ax = fmaf(w[7], t.x, ax); ay = fmaf(w[7], t.y, ay);
    return make_float2(ax, ay);
}

// ---------------- main stencil iteration, direction specialized ----------------
template <bool SRC_IS_X0>
__global__ void __launch_bounds__(256)
iter_kernel_t() {
    int j = blockIdx.x * 32 + threadIdx.x;
    int i = blockIdx.y * 8  + threadIdx.y;
    int pix = i * WW + j;

    const float2* __restrict__ xin  = SRC_IS_X0 ? g_x0 : g_x1;
    float2*       __restrict__ xout = SRC_IS_X0 ? g_x1 : g_x0;

    uint4 q = g_wq[pix];
    float w[8];
    unpack_w8(q, w);

    float2 v = taps8(xin, i, j, w);

    // colored pixels (all-zero weights): never store — their slots already
    // hold b in both buffers (seeded by prep)
    if ((q.x | q.y | q.z | q.w) != 0u)
        xout[pix] = v;
}

// ---------------- fused last step + YIQ->RGB (reads g_x1: step 100 src) ----------
__global__ void __launch_bounds__(256)
iter_final_kernel(float* __restrict__ out) {
    int j = blockIdx.x * 32 + threadIdx.x;
    int i = blockIdx.y * 8  + threadIdx.y;
    int pix = i * WW + j;

    uint4 q = g_wq[pix];
    float w[8];
    unpack_w8(q, w);

    float2 v = taps8(g_x1, i, j, w);
    // colored pixels output RGB of their (constant) value b
    if ((q.x | q.y | q.z | q.w) == 0u)
        v = g_x1[pix];

    float y = g_Y[pix];
    float I = v.x, Q = v.y;
    float r = y + 0.9468822170900693f  * I + 0.6235565819861433f * Q;
    float g = y - 0.27478764629897834f * I - 0.6356910791873801f * Q;
    float b = y - 1.1085450346420322f  * I + 1.7090069284064666f * Q;
    int o = 3 * pix;
    out[o+0] = fminf(fmaxf(r, 0.0f), 1.0f) * 255.0f;
    out[o+1] = fminf(fmaxf(g, 0.0f), 1.0f) * 255.0f;
    out[o+2] = fminf(fmaxf(b, 0.0f), 1.0f) * 255.0f;
}

extern "C" void kernel_launch(void* const* d_in, const int* in_sizes, int n_in,
                              void* d_out, int out_size) {
    const float* gray = (const float*)d_in[0];
    const float* app  = (const float*)d_in[1];
    float* out = (float*)d_out;

    int threads = 256;
    int blocks1d = (NPIX + threads - 1) / threads;

    prep_kernel<<<blocks1d, threads>>>(gray, app);

    dim3 blk(32, 8);
    dim3 grd(WW / 32, HH / 8);
    // 99 normal steps: it=0 reads x0 (even it -> src x0), alternating
    for (int it = 0; it < N_ITERS - 1; it++) {
        if ((it & 1) == 0) iter_kernel_t<true ><<<grd, blk>>>();
        else               iter_kernel_t<false><<<grd, blk>>>();
    }
    // it=98 (even) wrote g_x1; step 100 reads g_x1, fused with RGB conversion
    iter_final_kernel<<<grd, blk>>>(out);
}